// round 2
// baseline (speedup 1.0000x reference)
#include <cuda_runtime.h>

// Problem constants (SparseLinear: B x IN input, O outputs each reading K sparse features)
#define B_DIM 2048
#define IN_DIM 8192
#define O_DIM 4096
#define K_DIM 64

// 64 MB transposed copy of x: xt[i][b]  (b contiguous -> coalesced gather along b)
__device__ float g_xt[(size_t)IN_DIM * B_DIM];

// ---------------------------------------------------------------------------
// Kernel 1: transpose x[B, IN] -> g_xt[IN, B]. Standard 32x32 smem tile.
// ---------------------------------------------------------------------------
__global__ __launch_bounds__(256) void transpose_kernel(const float* __restrict__ x) {
    __shared__ float tile[32][33];  // +1 pad: conflict-free transposed read
    const int i0 = blockIdx.x * 32;  // IN dim
    const int b0 = blockIdx.y * 32;  // B dim
    const int tx = threadIdx.x;      // 0..31
    const int ty = threadIdx.y;      // 0..7

    // Coalesced read over IN (tx)
#pragma unroll
    for (int j = 0; j < 4; j++) {
        tile[ty + j * 8][tx] = x[(size_t)(b0 + ty + j * 8) * IN_DIM + (i0 + tx)];
    }
    __syncthreads();
    // Coalesced write over B (tx)
#pragma unroll
    for (int j = 0; j < 4; j++) {
        g_xt[(size_t)(i0 + ty + j * 8) * B_DIM + (b0 + tx)] = tile[tx][ty + j * 8];
    }
}

// ---------------------------------------------------------------------------
// Kernel 2: gather + weighted reduce.
// Block: 256 threads, each owns 4 consecutive b (one float4 column chunk)
//   -> block covers 1024 consecutive b. OT=64 outputs per block.
// Grid: (B/1024, O/OT) = (2, 64) = 128 blocks = one full wave.
// idx staged in smem PRE-MULTIPLIED by row stride (B/4 float4s) -> inner loop
// address math is a single IADD. OACC=4 o's accumulated simultaneously -> 4
// independent LDG.128 per k step, x4 k-unroll -> deep MLP.
// ---------------------------------------------------------------------------
#define OT 64
#define OACC 4
#define NTHR 256

__global__ __launch_bounds__(NTHR) void gather_kernel(const int* __restrict__ indices,
                                                      const float* __restrict__ weight,
                                                      const float* __restrict__ bias,
                                                      float* __restrict__ out) {
    __shared__ int s_idx[OT * K_DIM];   // 16 KB (premultiplied row offsets)
    __shared__ float s_w[OT * K_DIM];   // 16 KB

    const int tid = threadIdx.x;
    const int obase = blockIdx.y * OT;
    const int b4 = blockIdx.x * NTHR + tid;  // float4 index within an xt row
    const int brow = b4 * 4;                 // first of this thread's 4 b's

    // Stage this block's indices + weights (coalesced, once)
    for (int t = tid; t < OT * K_DIM; t += NTHR) {
        s_idx[t] = indices[(size_t)obase * K_DIM + t] * (B_DIM / 4);
        s_w[t] = weight[(size_t)obase * K_DIM + t];
    }
    __syncthreads();

    const float4* __restrict__ xt4 = (const float4*)g_xt;

    for (int og = 0; og < OT; og += OACC) {
        float acc[OACC][4];
#pragma unroll
        for (int j = 0; j < OACC; j++) {
            acc[j][0] = 0.f; acc[j][1] = 0.f; acc[j][2] = 0.f; acc[j][3] = 0.f;
        }

#pragma unroll 4
        for (int k = 0; k < K_DIM; k++) {
#pragma unroll
            for (int j = 0; j < OACC; j++) {
                const int so = (og + j) * K_DIM + k;
                const int rowoff = s_idx[so];     // already idx * (B_DIM/4)
                const float w = s_w[so];
                const float4 v = xt4[rowoff + b4];  // coalesced along b
                acc[j][0] += v.x * w;
                acc[j][1] += v.y * w;
                acc[j][2] += v.z * w;
                acc[j][3] += v.w * w;
            }
        }

        // bias for the 4 o's of this group (broadcast loads)
        float bv[OACC];
#pragma unroll
        for (int j = 0; j < OACC; j++) bv[j] = bias[obase + og + j];

        // Write out[b][o..o+3] as one float4 per b (4 per thread)
#pragma unroll
        for (int bb = 0; bb < 4; bb++) {
            float4 v;
            v.x = acc[0][bb] + bv[0];
            v.y = acc[1][bb] + bv[1];
            v.z = acc[2][bb] + bv[2];
            v.w = acc[3][bb] + bv[3];
            *(float4*)(out + (size_t)(brow + bb) * O_DIM + obase + og) = v;
        }
    }
}

// ---------------------------------------------------------------------------
// Launch
// ---------------------------------------------------------------------------
extern "C" void kernel_launch(void* const* d_in, const int* in_sizes, int n_in,
                              void* d_out, int out_size) {
    (void)in_sizes; (void)n_in; (void)out_size;
    const float* x = (const float*)d_in[0];
    const int* indices = (const int*)d_in[1];
    const float* weight = (const float*)d_in[2];
    const float* bias = (const float*)d_in[3];
    float* out = (float*)d_out;

    dim3 tb(32, 8);
    dim3 tg(IN_DIM / 32, B_DIM / 32);  // (256, 64)
    transpose_kernel<<<tg, tb>>>(x);

    dim3 gg(B_DIM / (NTHR * 4), O_DIM / OT);  // (2, 64)
    gather_kernel<<<gg, NTHR>>>(indices, weight, bias, out);
}

// round 3
// speedup vs baseline: 2.3069x; 2.3069x over previous
#include <cuda_runtime.h>

// Problem constants (SparseLinear: B x IN input, O outputs each reading K sparse features)
#define B_DIM 2048
#define IN_DIM 8192
#define O_DIM 4096
#define K_DIM 64

// 64 MB transposed copy of x: xt[i][b]  (b contiguous -> coalesced gather along b)
__device__ float g_xt[(size_t)IN_DIM * B_DIM];

// ---------------------------------------------------------------------------
// Kernel 1: transpose x[B, IN] -> g_xt[IN, B]. Standard 32x32 smem tile.
// ---------------------------------------------------------------------------
__global__ __launch_bounds__(256) void transpose_kernel(const float* __restrict__ x) {
    __shared__ float tile[32][33];  // +1 pad: conflict-free transposed read
    const int i0 = blockIdx.x * 32;  // IN dim
    const int b0 = blockIdx.y * 32;  // B dim
    const int tx = threadIdx.x;      // 0..31
    const int ty = threadIdx.y;      // 0..7

#pragma unroll
    for (int j = 0; j < 4; j++) {
        tile[ty + j * 8][tx] = x[(size_t)(b0 + ty + j * 8) * IN_DIM + (i0 + tx)];
    }
    __syncthreads();
#pragma unroll
    for (int j = 0; j < 4; j++) {
        g_xt[(size_t)(i0 + ty + j * 8) * B_DIM + (b0 + tx)] = tile[tx][ty + j * 8];
    }
}

// ---------------------------------------------------------------------------
// Kernel 2: gather + weighted reduce.
// R2 ncu: occ=12.4%, issue=9.6%, L2=25% -> LATENCY-bound, grid too small.
// R3 fix: OT 64->16 => grid (2, 256) = 512 CTAs, smem 8KB, 4 CTAs/SM
//         (__launch_bounds__(256,4)) => 32 warps/SM, 4x occupancy.
// Block: 256 threads, each owns 4 consecutive b (one float4) -> 1024 b/block.
// idx staged in smem PRE-MULTIPLIED by row stride; OACC=4 o's accumulated
// simultaneously, k-unroll 4 -> up to 16 independent LDG.128 batched.
// ---------------------------------------------------------------------------
#define OT 16
#define OACC 4
#define NTHR 256

__global__ __launch_bounds__(NTHR, 4) void gather_kernel(const int* __restrict__ indices,
                                                         const float* __restrict__ weight,
                                                         const float* __restrict__ bias,
                                                         float* __restrict__ out) {
    __shared__ int s_idx[OT * K_DIM];   // 4 KB (premultiplied row offsets)
    __shared__ float s_w[OT * K_DIM];   // 4 KB

    const int tid = threadIdx.x;
    const int obase = blockIdx.y * OT;
    const int b4 = blockIdx.x * NTHR + tid;  // float4 index within an xt row
    const int brow = b4 * 4;                 // first of this thread's 4 b's

    // Stage this block's indices + weights (coalesced, once)
    for (int t = tid; t < OT * K_DIM; t += NTHR) {
        s_idx[t] = indices[(size_t)obase * K_DIM + t] * (B_DIM / 4);
        s_w[t] = weight[(size_t)obase * K_DIM + t];
    }
    __syncthreads();

    const float4* __restrict__ xt4 = (const float4*)g_xt;

    for (int og = 0; og < OT; og += OACC) {
        float acc[OACC][4];
#pragma unroll
        for (int j = 0; j < OACC; j++) {
            acc[j][0] = 0.f; acc[j][1] = 0.f; acc[j][2] = 0.f; acc[j][3] = 0.f;
        }

#pragma unroll 4
        for (int k = 0; k < K_DIM; k++) {
#pragma unroll
            for (int j = 0; j < OACC; j++) {
                const int so = (og + j) * K_DIM + k;
                const int rowoff = s_idx[so];       // already idx * (B_DIM/4)
                const float w = s_w[so];
                const float4 v = xt4[rowoff + b4];  // coalesced along b
                acc[j][0] += v.x * w;
                acc[j][1] += v.y * w;
                acc[j][2] += v.z * w;
                acc[j][3] += v.w * w;
            }
        }

        float bv[OACC];
#pragma unroll
        for (int j = 0; j < OACC; j++) bv[j] = bias[obase + og + j];

#pragma unroll
        for (int bb = 0; bb < 4; bb++) {
            float4 v;
            v.x = acc[0][bb] + bv[0];
            v.y = acc[1][bb] + bv[1];
            v.z = acc[2][bb] + bv[2];
            v.w = acc[3][bb] + bv[3];
            *(float4*)(out + (size_t)(brow + bb) * O_DIM + obase + og) = v;
        }
    }
}

// ---------------------------------------------------------------------------
// Launch
// ---------------------------------------------------------------------------
extern "C" void kernel_launch(void* const* d_in, const int* in_sizes, int n_in,
                              void* d_out, int out_size) {
    (void)in_sizes; (void)n_in; (void)out_size;
    const float* x = (const float*)d_in[0];
    const int* indices = (const int*)d_in[1];
    const float* weight = (const float*)d_in[2];
    const float* bias = (const float*)d_in[3];
    float* out = (float*)d_out;

    dim3 tb(32, 8);
    dim3 tg(IN_DIM / 32, B_DIM / 32);  // (256, 64)
    transpose_kernel<<<tg, tb>>>(x);

    dim3 gg(B_DIM / (NTHR * 4), O_DIM / OT);  // (2, 256) = 512 CTAs
    gather_kernel<<<gg, NTHR>>>(indices, weight, bias, out);
}

// round 4
// speedup vs baseline: 3.2879x; 1.4252x over previous
#include <cuda_runtime.h>
#include <cuda_fp16.h>

// Problem constants (SparseLinear: B x IN input, O outputs each reading K sparse features)
#define B_DIM 2048
#define IN_DIM 8192
#define O_DIM 4096
#define K_DIM 64

// 32 MB transposed fp16 copy of x: xth[i][b]  (b contiguous -> coalesced gather,
// half the bytes of fp32; L2-resident with room to spare)
__device__ __half g_xth[(size_t)IN_DIM * B_DIM];

// ---------------------------------------------------------------------------
// Kernel 1: transpose+convert x[B, IN] f32 -> g_xth[IN, B] f16.
// ---------------------------------------------------------------------------
__global__ __launch_bounds__(256) void transpose_kernel(const float* __restrict__ x) {
    __shared__ float tile[32][33];
    const int i0 = blockIdx.x * 32;  // IN dim
    const int b0 = blockIdx.y * 32;  // B dim
    const int tx = threadIdx.x;
    const int ty = threadIdx.y;

#pragma unroll
    for (int j = 0; j < 4; j++) {
        tile[ty + j * 8][tx] = x[(size_t)(b0 + ty + j * 8) * IN_DIM + (i0 + tx)];
    }
    __syncthreads();
#pragma unroll
    for (int j = 0; j < 4; j++) {
        g_xth[(size_t)(i0 + ty + j * 8) * B_DIM + (b0 + tx)] = __float2half(tile[tx][ty + j * 8]);
    }
}

// ---------------------------------------------------------------------------
// Kernel 2: gather + weighted reduce on fp16 xt, fp32 accumulate.
// Thread owns 8 consecutive b (one uint4 = 8 halves) -> block covers all 2048 b.
// grid = (1, O/OT) = 512 CTAs. OACC=2 o's in flight, k-unroll 4 -> 8
// independent LDG.128 batched per warp. Warp reads 512B contiguous per load.
// ---------------------------------------------------------------------------
#define OT 8
#define OACC 2
#define NTHR 256

__global__ __launch_bounds__(NTHR, 4) void gather_kernel(const int* __restrict__ indices,
                                                         const float* __restrict__ weight,
                                                         const float* __restrict__ bias,
                                                         float* __restrict__ out) {
    __shared__ int s_idx[OT * K_DIM];   // 2 KB (premultiplied uint4-row offsets)
    __shared__ float s_w[OT * K_DIM];   // 2 KB

    const int tid = threadIdx.x;
    const int obase = blockIdx.y * OT;
    const int brow = tid * 8;  // first of this thread's 8 b's

    for (int t = tid; t < OT * K_DIM; t += NTHR) {
        s_idx[t] = indices[(size_t)obase * K_DIM + t] * (B_DIM / 8);  // uint4 stride per row
        s_w[t] = weight[(size_t)obase * K_DIM + t];
    }
    __syncthreads();

    const uint4* __restrict__ xt8 = (const uint4*)g_xth;

    for (int og = 0; og < OT; og += OACC) {
        float acc[OACC][8];
#pragma unroll
        for (int j = 0; j < OACC; j++)
#pragma unroll
            for (int q = 0; q < 8; q++) acc[j][q] = 0.f;

#pragma unroll 4
        for (int k = 0; k < K_DIM; k++) {
#pragma unroll
            for (int j = 0; j < OACC; j++) {
                const int so = (og + j) * K_DIM + k;
                const int rowoff = s_idx[so];        // already idx * (B_DIM/8)
                const float w = s_w[so];
                const uint4 v = xt8[rowoff + tid];   // 8 halves, coalesced along b
                const __half2* h = (const __half2*)&v;
#pragma unroll
                for (int q = 0; q < 4; q++) {
                    const float2 f = __half22float2(h[q]);
                    acc[j][2 * q + 0] += f.x * w;
                    acc[j][2 * q + 1] += f.y * w;
                }
            }
        }

        float bv[OACC];
#pragma unroll
        for (int j = 0; j < OACC; j++) bv[j] = bias[obase + og + j];

        // out[b][og..og+1] as float2, for each of this thread's 8 b's
#pragma unroll
        for (int bb = 0; bb < 8; bb++) {
            float2 v;
            v.x = acc[0][bb] + bv[0];
            v.y = acc[1][bb] + bv[1];
            *(float2*)(out + (size_t)(brow + bb) * O_DIM + obase + og) = v;
        }
    }
}

// ---------------------------------------------------------------------------
// Launch
// ---------------------------------------------------------------------------
extern "C" void kernel_launch(void* const* d_in, const int* in_sizes, int n_in,
                              void* d_out, int out_size) {
    (void)in_sizes; (void)n_in; (void)out_size;
    const float* x = (const float*)d_in[0];
    const int* indices = (const int*)d_in[1];
    const float* weight = (const float*)d_in[2];
    const float* bias = (const float*)d_in[3];
    float* out = (float*)d_out;

    dim3 tb(32, 8);
    dim3 tg(IN_DIM / 32, B_DIM / 32);  // (256, 64)
    transpose_kernel<<<tg, tb>>>(x);

    dim3 gg(1, O_DIM / OT);  // (1, 512)
    gather_kernel<<<gg, NTHR>>>(indices, weight, bias, out);
}